// round 15
// baseline (speedup 1.0000x reference)
#include <cuda_runtime.h>
#include <float.h>
#include <stdint.h>

// STCA loss — fused kernel, integer bitmask spike scan, LDGSTS ring.
//  r15 = r13 with TT 16->32 (single-variable test of the DRAM-granularity
//  theory: four scheduling changes were all neutral at ~5.1TB/s; the TT trend
//  TT=8->64us, TT=16->53us suggests bytes-per-stream-step is the real cap).
//  S_CHUNKS=8 (chunk=256), TR_PB=16, TPB=128, 2048 blocks. TT=32 (128B rows =
//  full L2 line per stream-step, half the per-tile overhead), PITCH=36
//  (conflict-free LDS.128), NBUF=2 -> 36.9KB smem -> 6 blocks/SM.
//  Warp stages its own 32 rows via cp.async (8 x 16B per lane per tile,
//  4 full 128B lines per instruction), __syncwarp only in the hot loop.
//  Integer-only monoid; winning cluster's positive mean recomputed deferred.
// Output: d_out[0] = loss, d_out[1 + trace] = num_clusters as float.

#define B_DIM 128
#define N_DIM 256
#define T_DIM 2048
#define C_GAP 3
#define NTRACE (B_DIM * N_DIM)        // 32768

#define S_CHUNKS 8
#define CHUNK_T  (T_DIM / S_CHUNKS)   // 256
#define TR_PB    16                   // traces per block
#define TPB      (TR_PB * S_CHUNKS)   // 128 threads
#define TT       32                   // timesteps per tile (128B per row-tile)
#define NTILE    (CHUNK_T / TT)       // 8
#define PITCH    36                   // floats per smem row (144B, conflict-free)
#define TILE_FLOATS (TPB * PITCH)     // 4608
#define TILE_BYTES  (TILE_FLOATS * 4) // 18432
#define NBUF     2                    // 36864 B total -> 6 blocks/SM
#define NBLOCKS  (NTRACE / TR_PB)     // 2048

#define SENT (1 << 30)

__device__ float        g_partial[NBLOCKS];
__device__ unsigned int g_count;      // zero-init; reset each replay by last block

__device__ __forceinline__ void cp_async16(uint32_t saddr, const float* gptr) {
    asm volatile("cp.async.cg.shared.global [%0], [%1], 16;\n" :: "r"(saddr), "l"(gptr));
}
__device__ __forceinline__ void cp_commit() { asm volatile("cp.async.commit_group;\n"); }
template <int N>
__device__ __forceinline__ void cp_wait() { asm volatile("cp.async.wait_group %0;\n" :: "n"(N)); }

__global__ void __launch_bounds__(TPB, 6)
stca_fused(const float* __restrict__ vmem,
           const int*   __restrict__ labels,
           float*       __restrict__ out)
{
    __shared__ float sm[NBUF * TILE_FLOATS];
    __shared__ bool  amLast;

    const int tid       = threadIdx.x;
    const int traceBase = blockIdx.x * TR_PB;
    const int c         = tid >> 4;        // chunk 0..7 (row = tid)
    const int wid       = tid >> 5;        // warp stages rows 32w..32w+31
    const int lane      = tid & 31;

    // ---- warp-local cp.async mapping: 8 x 16B per lane per tile ----
    // lane: tq = lane&7 (float4 column 0..7), rl0 = lane>>3 (0..3); rows rl0+4q.
    const int tq  = lane & 7;
    const int rl0 = lane >> 3;
    const float* gbase[8];
    uint32_t     sbase[8];
    #pragma unroll
    for (int q = 0; q < 8; q++) {
        const int r   = 32 * wid + rl0 + 4 * q;    // block-local row
        const int rtr = r & 15, rc = r >> 4;
        gbase[q] = vmem + (size_t)(traceBase + rtr) * T_DIM + rc * CHUNK_T + tq * 4;
        sbase[q] = (uint32_t)__cvta_generic_to_shared(sm) + (r * PITCH + tq * 4) * 4;
    }

    // prologue: tiles 0,1 in flight
    #pragma unroll
    for (int p = 0; p < NBUF; p++) {
        #pragma unroll
        for (int q = 0; q < 8; q++) cp_async16(sbase[q] + p * TILE_BYTES, gbase[q] + p * TT);
        cp_commit();
    }

    // ---- scan state (ALL integer; times are GLOBAL t) ----
    int last  = -1000000;                  // global time of previous spike
    int k = 0, ft = -1;
    int curc = 0, curst = 0;               // open cluster: count, start time
    int Fc = 0,    Fst = 0, Fen = 0;       // first cluster (count, start, end)
    int Ic = SENT, Ist = 0, Ien = 0;       // best interior cluster

    const float* myrow0 = sm + tid * PITCH;
    const int gchunk = c * CHUNK_T;        // global time base of my chunk
    int buf = 0;

    #pragma unroll 1
    for (int tile = 0; tile < NTILE; tile++) {
        if (tile < NTILE - 1) cp_wait<1>(); else cp_wait<0>();
        __syncwarp();                      // producers' smem writes visible warp-wide

        const float* r = myrow0 + buf * TILE_FLOATS;

        // 32-bit spike mask from sign bits: PRMT pack + magic multiply.
        uint32_t nm = 0;
        #pragma unroll
        for (int j = 0; j < 8; j++) {
            const uint4 u = *reinterpret_cast<const uint4*>(r + 4 * j);
            uint32_t t0 = __byte_perm(u.x, u.y, 0x0073);
            uint32_t t1 = __byte_perm(u.z, u.w, 0x0073);
            uint32_t sb = __byte_perm(t0, t1, 0x5410);
            sb &= 0x80808080u;
            nm |= ((sb * 0x00204081u) >> 28) << (4 * j);
        }
        uint32_t m = ~nm;                  // spike mask (v >= 0), full 32 bits

        if (m) {
            const int wb = gchunk + tile * TT;
            if (ft < 0) ft = wb + __ffs(m) - 1;
            do {
                const int i = __ffs(m) - 1;
                m &= m - 1;
                const int  tg = wb + i;
                const bool nw = (tg - last) > C_GAP;
                const bool cF = nw && (k == 1);
                const bool cI = nw && (k >= 2) && (curc < Ic);
                Fc = cF ? curc : Fc;  Fst = cF ? curst : Fst;  Fen = cF ? last : Fen;
                Ic = cI ? curc : Ic;  Ist = cI ? curst : Ist;  Ien = cI ? last : Ien;
                k += nw;
                curst = nw ? tg : curst;
                curc  = (nw ? 0 : curc) + 1;
                last  = tg;
            } while (m);
        }

        __syncwarp();                      // all lanes done reading buf
        if (tile + NBUF < NTILE) {         // refill buf with tile+2
            const uint32_t soff = buf * TILE_BYTES;
            const int goff = (tile + NBUF) * TT;
            #pragma unroll
            for (int q = 0; q < 8; q++) cp_async16(sbase[q] + soff, gbase[q] + goff);
            cp_commit();
        }
        buf ^= 1;
    }

    if (k == 1) { Fc = curc; Fst = curst; Fen = last; }
    // open/last cluster L = (curc, curst, last)

    // Lazy vmax: only when the chunk has NO spikes. Rescan gmem.
    float vmax = -FLT_MAX;
    if (k == 0) {
        const float* g = vmem + (size_t)(traceBase + (tid & 15)) * T_DIM + gchunk;
        #pragma unroll 1
        for (int j = 0; j < CHUNK_T; j++) vmax = fmaxf(vmax, g[j]);
    }

    // ---- chunk summaries to smem: [128][16] ----
    __syncthreads();
    float* summ = sm;
    {
        float* w = summ + tid * 16;
        w[0]  = vmax;
        w[1]  = (float)ft;                 // -1 if no spike (k==0)
        w[2]  = (float)last;               // valid iff k>0
        w[3]  = (float)k;
        w[4]  = (float)Fc;   w[5]  = (float)Fst;  w[6]  = (float)Fen;
        w[7]  = (float)Ic;   w[8]  = (float)Ist;  w[9]  = (float)Ien;
        w[10] = (float)curc; w[11] = (float)curst; w[12] = (float)last;
    }
    __syncthreads();

    // ---- merge 8 chunk summaries per trace (threads 0..15) ----
    float* red = sm + TPB * 16;
    float contrib = 0.0f;
    if (tid < TR_PB) {
        float vx = -FLT_MAX;
        int last_t = -1000000, nclust = 0;
        int opc = -1, opst = 0;                      // open cluster (count, start)
        int bc = SENT, bst = 0, ben = 0;             // best closed (count, span)
        #pragma unroll
        for (int cc = 0; cc < S_CHUNKS; cc++) {
            const float* w = summ + (cc * TR_PB + tid) * 16;
            vx = fmaxf(vx, w[0]);
            const int kk = (int)w[3];
            if (kk == 0) continue;
            const int ftc = (int)w[1], ltc = (int)w[2];
            const int fC = (int)w[4],  fS = (int)w[5],  fE = (int)w[6];
            const int iC = (int)w[7],  iS = (int)w[8],  iE = (int)w[9];
            const int lC = (int)w[10], lS = (int)w[11];

            if (opc >= 0 && (ftc - last_t) <= C_GAP) {
                const int mc = opc + fC;             // merged: span (opst, fE)
                if (kk == 1) { opc = mc; }
                else {
                    if (mc < bc) { bc = mc; bst = opst; ben = fE; }
                    if (iC < bc) { bc = iC; bst = iS;   ben = iE; }
                    opc = lC; opst = lS;
                    nclust += kk - 1;
                }
            } else {
                if (opc >= 0 && opc < bc) { bc = opc; bst = opst; ben = last_t; }
                nclust += kk;
                if (kk == 1) { opc = fC; opst = fS; }
                else {
                    if (fC < bc) { bc = fC; bst = fS; ben = fE; }
                    if (iC < bc) { bc = iC; bst = iS; ben = iE; }
                    opc = lC; opst = lS;
                }
            }
            last_t = ltc;
        }
        if (opc >= 0 && opc < bc) { bc = opc; bst = opst; ben = last_t; }

        const int trace = traceBase + tid;
        out[1 + trace] = (float)nclust;

        const int b = trace / N_DIM;
        const int n = trace - b * N_DIM;
        if (n == labels[b]) {
            if (nclust == 0) contrib = -vx;
        } else if (nclust > 0) {
            // Deferred: mean of v>0 over the winning cluster's span (ascending t,
            // same summation order as the direct scan -> identical loss terms).
            const float* g = vmem + (size_t)trace * T_DIM;
            float s = 0.0f; int pc = 0;
            #pragma unroll 1
            for (int t = bst; t <= ben; t++) {
                const float v = g[t];
                if (v > 0.0f) { s += v; pc++; }
            }
            contrib = s / fmaxf((float)pc, 1.0f);
        }
    }

    // ---- block tree reduction (128 threads; >=16 contribute 0) ----
    red[tid] = contrib;
    __syncthreads();
    #pragma unroll
    for (int off = TPB / 2; off > 0; off >>= 1) {
        if (tid < off) red[tid] += red[tid + off];
        __syncthreads();
    }
    if (tid == 0) {
        g_partial[blockIdx.x] = red[0];
        __threadfence();
        amLast = (atomicAdd(&g_count, 1u) == (unsigned)(gridDim.x - 1));
    }
    __syncthreads();

    if (amLast) {
        __threadfence();
        float x = 0.0f;
        #pragma unroll
        for (int j = 0; j < NBLOCKS / TPB; j++) x += g_partial[tid + TPB * j];
        red[tid] = x;
        __syncthreads();
        #pragma unroll
        for (int off = TPB / 2; off > 0; off >>= 1) {
            if (tid < off) red[tid] += red[tid + off];
            __syncthreads();
        }
        if (tid == 0) {
            out[0] = red[0];
            g_count = 0;                   // reset for next graph replay
        }
    }
}

extern "C" void kernel_launch(void* const* d_in, const int* in_sizes, int n_in,
                              void* d_out, int out_size)
{
    const float* vmem   = (const float*)d_in[0];
    // d_in[1] (vlastmem) unused by the forward computation.
    const int*   labels = (const int*)d_in[2];
    float*       out    = (float*)d_out;

    stca_fused<<<NBLOCKS, TPB>>>(vmem, labels, out);
}

// round 16
// speedup vs baseline: 1.0400x; 1.0400x over previous
#include <cuda_runtime.h>
#include <float.h>
#include <stdint.h>

// STCA loss — fused kernel, integer bitmask spike scan, LDGSTS ring.
//  r16 = r13 (best: 53.2us) with ONE change: cp.async carries the L2::256B
//  fetch hint. Theory: all five scheduling/width experiments pinned at
//  ~5.1TB/s because each per-trace stream touches only 64-128B per DRAM row
//  activation (row-buffer thrash across ~32K interleaved streams). The hint
//  makes DRAM fetch 256B per touch; the next 3 tile-fetches of that row hit L2.
//  Geometry: S_CHUNKS=8 (chunk=256), TR_PB=16, TPB=128, 2048 blocks, TT=16,
//  PITCH=20 (conflict-free LDS.128), NBUF=2 -> 11 blocks/SM, 44 warps/SM.
//  Integer-only monoid; winning cluster's positive mean recomputed deferred;
//  vmax lazy for spikeless chunks.
// Output: d_out[0] = loss, d_out[1 + trace] = num_clusters as float.

#define B_DIM 128
#define N_DIM 256
#define T_DIM 2048
#define C_GAP 3
#define NTRACE (B_DIM * N_DIM)        // 32768

#define S_CHUNKS 8
#define CHUNK_T  (T_DIM / S_CHUNKS)   // 256
#define TR_PB    16                   // traces per block
#define TPB      (TR_PB * S_CHUNKS)   // 128 threads
#define TT       16                   // timesteps per tile (64B per row-tile)
#define NTILE    (CHUNK_T / TT)       // 16
#define PITCH    20                   // floats per smem row (80B, conflict-free)
#define TILE_FLOATS (TPB * PITCH)     // 2560
#define TILE_BYTES  (TILE_FLOATS * 4) // 10240
#define NBUF     2                    // 20480 B total -> 11 blocks/SM
#define NBLOCKS  (NTRACE / TR_PB)     // 2048

#define SENT (1 << 30)

__device__ float        g_partial[NBLOCKS];
__device__ unsigned int g_count;      // zero-init; reset each replay by last block

__device__ __forceinline__ void cp_async16(uint32_t saddr, const float* gptr) {
    asm volatile("cp.async.cg.shared.global.L2::256B [%0], [%1], 16;\n"
                 :: "r"(saddr), "l"(gptr));
}
__device__ __forceinline__ void cp_commit() { asm volatile("cp.async.commit_group;\n"); }
template <int N>
__device__ __forceinline__ void cp_wait() { asm volatile("cp.async.wait_group %0;\n" :: "n"(N)); }

__global__ void __launch_bounds__(TPB, 11)
stca_fused(const float* __restrict__ vmem,
           const int*   __restrict__ labels,
           float*       __restrict__ out)
{
    __shared__ float sm[NBUF * TILE_FLOATS];
    __shared__ bool  amLast;

    const int tid       = threadIdx.x;
    const int traceBase = blockIdx.x * TR_PB;
    const int c         = tid >> 4;        // chunk 0..7 (row = tid)
    const int wid       = tid >> 5;        // warp stages rows 32w..32w+31
    const int lane      = tid & 31;

    // ---- warp-local cp.async mapping: 4 x 16B per lane per tile ----
    const int tq  = lane & 3;              // float4 column 0..3 of the 64B row-tile
    const int rl0 = lane >> 2;             // 0..7
    const float* gbase[4];
    uint32_t     sbase[4];
    #pragma unroll
    for (int q = 0; q < 4; q++) {
        const int r   = 32 * wid + rl0 + 8 * q;    // block-local row
        const int rtr = r & 15, rc = r >> 4;
        gbase[q] = vmem + (size_t)(traceBase + rtr) * T_DIM + rc * CHUNK_T + tq * 4;
        sbase[q] = (uint32_t)__cvta_generic_to_shared(sm) + (r * PITCH + tq * 4) * 4;
    }

    // prologue: tiles 0,1 in flight
    #pragma unroll
    for (int p = 0; p < NBUF; p++) {
        #pragma unroll
        for (int q = 0; q < 4; q++) cp_async16(sbase[q] + p * TILE_BYTES, gbase[q] + p * TT);
        cp_commit();
    }

    // ---- scan state (ALL integer; times are GLOBAL t) ----
    int last  = -1000000;                  // global time of previous spike
    int k = 0, ft = -1;
    int curc = 0, curst = 0;               // open cluster: count, start time
    int Fc = 0,    Fst = 0, Fen = 0;       // first cluster (count, start, end)
    int Ic = SENT, Ist = 0, Ien = 0;       // best interior cluster

    const float* myrow0 = sm + tid * PITCH;
    const int gchunk = c * CHUNK_T;        // global time base of my chunk
    int buf = 0;

    #pragma unroll 1
    for (int tile = 0; tile < NTILE; tile++) {
        if (tile < NTILE - 1) cp_wait<1>(); else cp_wait<0>();
        __syncwarp();                      // producers' smem writes visible warp-wide

        const float* r = myrow0 + buf * TILE_FLOATS;

        // 16-bit spike mask from sign bits: PRMT pack + magic multiply.
        uint32_t nm = 0;
        #pragma unroll
        for (int j = 0; j < 4; j++) {
            const uint4 u = *reinterpret_cast<const uint4*>(r + 4 * j);
            uint32_t t0 = __byte_perm(u.x, u.y, 0x0073);
            uint32_t t1 = __byte_perm(u.z, u.w, 0x0073);
            uint32_t sb = __byte_perm(t0, t1, 0x5410);
            sb &= 0x80808080u;
            nm |= ((sb * 0x00204081u) >> 28) << (4 * j);
        }
        uint32_t m = (~nm) & 0xFFFFu;      // spike mask (v >= 0)

        if (m) {
            const int wb = gchunk + tile * TT;
            if (ft < 0) ft = wb + __ffs(m) - 1;
            do {
                const int i = __ffs(m) - 1;
                m &= m - 1;
                const int  tg = wb + i;
                const bool nw = (tg - last) > C_GAP;
                const bool cF = nw && (k == 1);
                const bool cI = nw && (k >= 2) && (curc < Ic);
                Fc = cF ? curc : Fc;  Fst = cF ? curst : Fst;  Fen = cF ? last : Fen;
                Ic = cI ? curc : Ic;  Ist = cI ? curst : Ist;  Ien = cI ? last : Ien;
                k += nw;
                curst = nw ? tg : curst;
                curc  = (nw ? 0 : curc) + 1;
                last  = tg;
            } while (m);
        }

        __syncwarp();                      // all lanes done reading buf
        if (tile + NBUF < NTILE) {         // refill buf with tile+2
            const uint32_t soff = buf * TILE_BYTES;
            const int goff = (tile + NBUF) * TT;
            #pragma unroll
            for (int q = 0; q < 4; q++) cp_async16(sbase[q] + soff, gbase[q] + goff);
            cp_commit();
        }
        buf ^= 1;
    }

    if (k == 1) { Fc = curc; Fst = curst; Fen = last; }
    // open/last cluster L = (curc, curst, last)

    // Lazy vmax: only when the chunk has NO spikes. Rescan gmem.
    float vmax = -FLT_MAX;
    if (k == 0) {
        const float* g = vmem + (size_t)(traceBase + (tid & 15)) * T_DIM + gchunk;
        #pragma unroll 1
        for (int j = 0; j < CHUNK_T; j++) vmax = fmaxf(vmax, g[j]);
    }

    // ---- chunk summaries to smem: [128][16] ----
    __syncthreads();
    float* summ = sm;
    {
        float* w = summ + tid * 16;
        w[0]  = vmax;
        w[1]  = (float)ft;                 // -1 if no spike (k==0)
        w[2]  = (float)last;               // valid iff k>0
        w[3]  = (float)k;
        w[4]  = (float)Fc;   w[5]  = (float)Fst;  w[6]  = (float)Fen;
        w[7]  = (float)Ic;   w[8]  = (float)Ist;  w[9]  = (float)Ien;
        w[10] = (float)curc; w[11] = (float)curst; w[12] = (float)last;
    }
    __syncthreads();

    // ---- merge 8 chunk summaries per trace (threads 0..15) ----
    float* red = sm + TPB * 16;
    float contrib = 0.0f;
    if (tid < TR_PB) {
        float vx = -FLT_MAX;
        int last_t = -1000000, nclust = 0;
        int opc = -1, opst = 0;                      // open cluster (count, start)
        int bc = SENT, bst = 0, ben = 0;             // best closed (count, span)
        #pragma unroll
        for (int cc = 0; cc < S_CHUNKS; cc++) {
            const float* w = summ + (cc * TR_PB + tid) * 16;
            vx = fmaxf(vx, w[0]);
            const int kk = (int)w[3];
            if (kk == 0) continue;
            const int ftc = (int)w[1], ltc = (int)w[2];
            const int fC = (int)w[4],  fS = (int)w[5],  fE = (int)w[6];
            const int iC = (int)w[7],  iS = (int)w[8],  iE = (int)w[9];
            const int lC = (int)w[10], lS = (int)w[11];

            if (opc >= 0 && (ftc - last_t) <= C_GAP) {
                const int mc = opc + fC;             // merged: span (opst, fE)
                if (kk == 1) { opc = mc; }
                else {
                    if (mc < bc) { bc = mc; bst = opst; ben = fE; }
                    if (iC < bc) { bc = iC; bst = iS;   ben = iE; }
                    opc = lC; opst = lS;
                    nclust += kk - 1;
                }
            } else {
                if (opc >= 0 && opc < bc) { bc = opc; bst = opst; ben = last_t; }
                nclust += kk;
                if (kk == 1) { opc = fC; opst = fS; }
                else {
                    if (fC < bc) { bc = fC; bst = fS; ben = fE; }
                    if (iC < bc) { bc = iC; bst = iS; ben = iE; }
                    opc = lC; opst = lS;
                }
            }
            last_t = ltc;
        }
        if (opc >= 0 && opc < bc) { bc = opc; bst = opst; ben = last_t; }

        const int trace = traceBase + tid;
        out[1 + trace] = (float)nclust;

        const int b = trace / N_DIM;
        const int n = trace - b * N_DIM;
        if (n == labels[b]) {
            if (nclust == 0) contrib = -vx;
        } else if (nclust > 0) {
            // Deferred: mean of v>0 over the winning cluster's span (ascending t,
            // same summation order as the direct scan -> identical loss terms).
            const float* g = vmem + (size_t)trace * T_DIM;
            float s = 0.0f; int pc = 0;
            #pragma unroll 1
            for (int t = bst; t <= ben; t++) {
                const float v = g[t];
                if (v > 0.0f) { s += v; pc++; }
            }
            contrib = s / fmaxf((float)pc, 1.0f);
        }
    }

    // ---- block tree reduction (128 threads; >=16 contribute 0) ----
    red[tid] = contrib;
    __syncthreads();
    #pragma unroll
    for (int off = TPB / 2; off > 0; off >>= 1) {
        if (tid < off) red[tid] += red[tid + off];
        __syncthreads();
    }
    if (tid == 0) {
        g_partial[blockIdx.x] = red[0];
        __threadfence();
        amLast = (atomicAdd(&g_count, 1u) == (unsigned)(gridDim.x - 1));
    }
    __syncthreads();

    if (amLast) {
        __threadfence();
        float x = 0.0f;
        #pragma unroll
        for (int j = 0; j < NBLOCKS / TPB; j++) x += g_partial[tid + TPB * j];
        red[tid] = x;
        __syncthreads();
        #pragma unroll
        for (int off = TPB / 2; off > 0; off >>= 1) {
            if (tid < off) red[tid] += red[tid + off];
            __syncthreads();
        }
        if (tid == 0) {
            out[0] = red[0];
            g_count = 0;                   // reset for next graph replay
        }
    }
}

extern "C" void kernel_launch(void* const* d_in, const int* in_sizes, int n_in,
                              void* d_out, int out_size)
{
    const float* vmem   = (const float*)d_in[0];
    // d_in[1] (vlastmem) unused by the forward computation.
    const int*   labels = (const int*)d_in[2];
    float*       out    = (float*)d_out;

    stca_fused<<<NBLOCKS, TPB>>>(vmem, labels, out);
}